// round 1
// baseline (speedup 1.0000x reference)
#include <cuda_runtime.h>
#include <math.h>

#define B_ 1024
#define S_ 512
#define D_ 768
#define FEAT 2304   // 3*D
#define H1 256
#define H2 64
#define NC 4
#define TM 8        // batches per MLP block

// Scratch: per-batch feature vector [e1(768) | e2(768) | cls(768)]
__device__ float g_feat[B_ * FEAT];

// ---------------------------------------------------------------------------
// Kernel 1: span means + cls copy.
// grid = (B, 2): blockIdx.x = batch, blockIdx.y = which span.
// 192 threads, each owns one float4 (4 cols) -> covers the full 768-col row.
// ---------------------------------------------------------------------------
__global__ __launch_bounds__(192) void span_kernel(
    const float* __restrict__ x,
    const int*   __restrict__ e1_span,
    const int*   __restrict__ e2_span,
    float*       __restrict__ feat)
{
    const int b = blockIdx.x;
    const int e = blockIdx.y;
    const int t = threadIdx.x;  // 0..191

    const int* sp = (e == 0) ? e1_span : e2_span;
    int lo = sp[2 * b];
    int hi = sp[2 * b + 1];
    if (hi < lo + 1) hi = lo + 1;
    const float inv = 1.0f / (float)(hi - lo);

    const float4* xb = (const float4*)(x + (size_t)b * S_ * D_);  // row s = xb + s*192

    float4 acc = make_float4(0.f, 0.f, 0.f, 0.f);

    int s = lo;
    // unroll-by-4: 4 independent in-flight loads per thread
    for (; s + 4 <= hi; s += 4) {
        float4 a0 = xb[(size_t)(s + 0) * 192 + t];
        float4 a1 = xb[(size_t)(s + 1) * 192 + t];
        float4 a2 = xb[(size_t)(s + 2) * 192 + t];
        float4 a3 = xb[(size_t)(s + 3) * 192 + t];
        acc.x += (a0.x + a1.x) + (a2.x + a3.x);
        acc.y += (a0.y + a1.y) + (a2.y + a3.y);
        acc.z += (a0.z + a1.z) + (a2.z + a3.z);
        acc.w += (a0.w + a1.w) + (a2.w + a3.w);
    }
    for (; s < hi; s++) {
        float4 a = xb[(size_t)s * 192 + t];
        acc.x += a.x; acc.y += a.y; acc.z += a.z; acc.w += a.w;
    }

    float4* fdst = (float4*)(feat + (size_t)b * FEAT + e * D_);
    fdst[t] = make_float4(acc.x * inv, acc.y * inv, acc.z * inv, acc.w * inv);

    if (e == 0) {
        // cls = x[b, 0, :]
        float4 c = xb[t];
        ((float4*)(feat + (size_t)b * FEAT + 2 * D_))[t] = c;
    }
}

// ---------------------------------------------------------------------------
// Kernel 2: fused MLP + softmax.
// grid = B/TM blocks, 256 threads. Thread j owns h1 column j for TM batches.
// feat staged through smem in 768-wide K-chunks (static smem < 48KB).
// ---------------------------------------------------------------------------
__global__ __launch_bounds__(256) void mlp_kernel(
    const float* __restrict__ feat,
    const float* __restrict__ W1, const float* __restrict__ b1,
    const float* __restrict__ W2, const float* __restrict__ b2,
    const float* __restrict__ W3, const float* __restrict__ b3,
    float*       __restrict__ out)
{
    __shared__ float sf[TM * 768];   // 24 KB: feat K-chunk
    __shared__ float sh1[TM * H1];   // 8 KB
    __shared__ float sh2[TM * H2];   // 2 KB

    const int j  = threadIdx.x;      // 0..255
    const int b0 = blockIdx.x * TM;

    float acc[TM];
    {
        const float bias = b1[j];
        #pragma unroll
        for (int m = 0; m < TM; m++) acc[m] = bias;
    }

    // ---- stage 1: h1 = relu(feat @ W1 + b1), K = 2304 in 3 chunks of 768 ----
    for (int chunk = 0; chunk < 3; chunk++) {
        // stage feat tile: TM*768 floats, coalesced
        for (int i = j; i < TM * 768; i += 256) {
            int m = i / 768, k = i % 768;
            sf[i] = feat[(size_t)(b0 + m) * FEAT + chunk * 768 + k];
        }
        __syncthreads();

        const float* W1c = W1 + (size_t)chunk * 768 * H1;
        #pragma unroll 4
        for (int k = 0; k < 768; k++) {
            float w = W1c[(size_t)k * H1 + j];   // coalesced across threads
            #pragma unroll
            for (int m = 0; m < TM; m++)
                acc[m] = fmaf(sf[m * 768 + k], w, acc[m]);  // smem broadcast
        }
        __syncthreads();
    }

    #pragma unroll
    for (int m = 0; m < TM; m++) sh1[m * H1 + j] = fmaxf(acc[m], 0.f);
    __syncthreads();

    // ---- stage 2: h2 = relu(h1 @ W2 + b2), 8x64 outputs, 2 per thread ----
    {
        const int j2 = j & 63;           // output column 0..63
        for (int m = j >> 6; m < TM; m += 4) {
            float a = b2[j2];
            #pragma unroll 8
            for (int k = 0; k < H1; k++)
                a = fmaf(sh1[m * H1 + k], W2[(size_t)k * H2 + j2], a);
            sh2[m * H2 + j2] = fmaxf(a, 0.f);
        }
    }
    __syncthreads();

    // ---- stage 3 + softmax: one thread per batch ----
    if (j < TM) {
        const int m = j;
        float l0 = b3[0], l1 = b3[1], l2 = b3[2], l3 = b3[3];
        #pragma unroll 8
        for (int k = 0; k < H2; k++) {
            float h = sh2[m * H2 + k];
            l0 = fmaf(h, W3[k * NC + 0], l0);
            l1 = fmaf(h, W3[k * NC + 1], l1);
            l2 = fmaf(h, W3[k * NC + 2], l2);
            l3 = fmaf(h, W3[k * NC + 3], l3);
        }
        float mx = fmaxf(fmaxf(l0, l1), fmaxf(l2, l3));
        float e0 = __expf(l0 - mx), e1v = __expf(l1 - mx);
        float e2v = __expf(l2 - mx), e3v = __expf(l3 - mx);
        float inv = 1.0f / (e0 + e1v + e2v + e3v);
        float* o = out + (size_t)(b0 + m) * NC;
        o[0] = e0 * inv; o[1] = e1v * inv; o[2] = e2v * inv; o[3] = e3v * inv;
    }
}

// ---------------------------------------------------------------------------
extern "C" void kernel_launch(void* const* d_in, const int* in_sizes, int n_in,
                              void* d_out, int out_size)
{
    const float* x       = (const float*)d_in[0];
    const int*   e1_span = (const int*)  d_in[1];
    const int*   e2_span = (const int*)  d_in[2];
    const float* W1      = (const float*)d_in[3];
    const float* b1      = (const float*)d_in[4];
    const float* W2      = (const float*)d_in[5];
    const float* b2      = (const float*)d_in[6];
    const float* W3      = (const float*)d_in[7];
    const float* b3      = (const float*)d_in[8];
    float* out = (float*)d_out;

    float* feat;
    cudaGetSymbolAddress((void**)&feat, g_feat);

    span_kernel<<<dim3(B_, 2), 192>>>(x, e1_span, e2_span, feat);
    mlp_kernel<<<B_ / TM, 256>>>(feat, W1, b1, W2, b2, W3, b3, out);
}

// round 3
// speedup vs baseline: 1.7191x; 1.7191x over previous
#include <cuda_runtime.h>
#include <math.h>

#define B_ 1024
#define S_ 512
#define D_ 768
#define FEAT 2304   // 3*D
#define H1 256
#define H2 64
#define NC 4
#define TM 8        // batches per stage1 block
#define KSPLIT 3
#define KCHUNK 768
#define KT 32       // K-tile staged in smem

// Scratch (no allocations allowed): feature vectors + stage1 partials
__device__ float g_feat[B_ * FEAT];                 // [b][e1|e2|cls]
__device__ float g_h1p[KSPLIT * B_ * H1];           // [chunk][b][j]

// ---------------------------------------------------------------------------
// Kernel 1: both span means + cls in ONE pass over the union of the spans.
// grid = B, 192 threads; thread t owns one float4 (cols 4t..4t+3).
// ---------------------------------------------------------------------------
__global__ __launch_bounds__(192) void span_kernel(
    const float* __restrict__ x,
    const int*   __restrict__ e1_span,
    const int*   __restrict__ e2_span,
    float*       __restrict__ feat)
{
    const int b = blockIdx.x;
    const int t = threadIdx.x;

    int lo1 = e1_span[2 * b], hi1 = e1_span[2 * b + 1];
    if (hi1 < lo1 + 1) hi1 = lo1 + 1;
    int lo2 = e2_span[2 * b], hi2 = e2_span[2 * b + 1];
    if (hi2 < lo2 + 1) hi2 = lo2 + 1;

    const float inv1 = 1.0f / (float)(hi1 - lo1);
    const float inv2 = 1.0f / (float)(hi2 - lo2);

    const float4* xb = (const float4*)(x + (size_t)b * S_ * D_);

    // union = [u_lo, u_hi) minus possible gap [g_lo, g_hi)
    const int u_lo = min(lo1, lo2);
    const int u_hi = max(hi1, hi2);
    int g_lo = min(hi1, hi2);
    int g_hi = max(lo1, lo2);
    if (g_hi < g_lo) { g_lo = u_hi; g_hi = u_hi; }   // no gap

    float4 a1 = make_float4(0.f, 0.f, 0.f, 0.f);
    float4 a2 = make_float4(0.f, 0.f, 0.f, 0.f);

    // two contiguous segments: [u_lo, g_lo) and [g_hi, u_hi)
    #pragma unroll 1
    for (int seg = 0; seg < 2; seg++) {
        const int s0 = (seg == 0) ? u_lo : g_hi;
        const int s1 = (seg == 0) ? g_lo : u_hi;
        int s = s0;
        for (; s + 4 <= s1; s += 4) {
            float4 r0 = xb[(size_t)(s + 0) * 192 + t];
            float4 r1 = xb[(size_t)(s + 1) * 192 + t];
            float4 r2 = xb[(size_t)(s + 2) * 192 + t];
            float4 r3 = xb[(size_t)(s + 3) * 192 + t];
            #pragma unroll
            for (int u = 0; u < 4; u++) {
                const int ss = s + u;
                const float4 r = (u == 0) ? r0 : (u == 1) ? r1 : (u == 2) ? r2 : r3;
                const float w1 = (ss >= lo1 && ss < hi1) ? 1.0f : 0.0f;
                const float w2 = (ss >= lo2 && ss < hi2) ? 1.0f : 0.0f;
                a1.x = fmaf(r.x, w1, a1.x); a1.y = fmaf(r.y, w1, a1.y);
                a1.z = fmaf(r.z, w1, a1.z); a1.w = fmaf(r.w, w1, a1.w);
                a2.x = fmaf(r.x, w2, a2.x); a2.y = fmaf(r.y, w2, a2.y);
                a2.z = fmaf(r.z, w2, a2.z); a2.w = fmaf(r.w, w2, a2.w);
            }
        }
        for (; s < s1; s++) {
            float4 r = xb[(size_t)s * 192 + t];
            const float w1 = (s >= lo1 && s < hi1) ? 1.0f : 0.0f;
            const float w2 = (s >= lo2 && s < hi2) ? 1.0f : 0.0f;
            a1.x = fmaf(r.x, w1, a1.x); a1.y = fmaf(r.y, w1, a1.y);
            a1.z = fmaf(r.z, w1, a1.z); a1.w = fmaf(r.w, w1, a1.w);
            a2.x = fmaf(r.x, w2, a2.x); a2.y = fmaf(r.y, w2, a2.y);
            a2.z = fmaf(r.z, w2, a2.z); a2.w = fmaf(r.w, w2, a2.w);
        }
    }

    float4* fb = (float4*)(feat + (size_t)b * FEAT);
    fb[t]           = make_float4(a1.x * inv1, a1.y * inv1, a1.z * inv1, a1.w * inv1);
    fb[192 + t]     = make_float4(a2.x * inv2, a2.y * inv2, a2.z * inv2, a2.w * inv2);
    fb[384 + t]     = xb[t];   // cls = row 0
}

// ---------------------------------------------------------------------------
// Kernel 2: stage-1 GEMM partials.  grid = (B/TM, KSPLIT), 256 threads.
// Block (mb, c) computes h1p[c][b0..b0+7][0..255] over K-chunk c (768 wide).
// feat tile staged TRANSPOSED in smem (LDS.128 feeds 4 accs),
// W1 tile (32x256) staged in smem -> inner loop has no global loads.
// ---------------------------------------------------------------------------
__global__ __launch_bounds__(256) void stage1_kernel(
    const float* __restrict__ feat,
    const float* __restrict__ W1,
    float*       __restrict__ h1p)
{
    __shared__ float sfT[KCHUNK * TM];   // [k][m] 24 KB
    __shared__ float sW[KT * H1];        // [kk][j] 32 KB

    const int j     = threadIdx.x;       // 0..255 = h1 column
    const int b0    = blockIdx.x * TM;
    const int chunk = blockIdx.y;

    // load feat tile transposed: global reads coalesced over k
    const float* fbase = feat + (size_t)b0 * FEAT + chunk * KCHUNK;
    for (int idx = j; idx < TM * KCHUNK; idx += 256) {
        const int m = idx / KCHUNK;
        const int k = idx % KCHUNK;
        sfT[k * TM + m] = fbase[(size_t)m * FEAT + k];
    }

    float acc[TM];
    #pragma unroll
    for (int m = 0; m < TM; m++) acc[m] = 0.f;

    const float* W1c = W1 + (size_t)chunk * KCHUNK * H1;

    __syncthreads();   // sfT ready

    for (int kt = 0; kt < KCHUNK; kt += KT) {
        // stage W tile: KT rows of 256, coalesced
        #pragma unroll
        for (int r = 0; r < KT; r++)
            sW[r * H1 + j] = W1c[(size_t)(kt + r) * H1 + j];
        __syncthreads();

        #pragma unroll
        for (int kk = 0; kk < KT; kk++) {
            const float w = sW[kk * H1 + j];
            const float4 f0 = *(const float4*)&sfT[(kt + kk) * TM];
            const float4 f1 = *(const float4*)&sfT[(kt + kk) * TM + 4];
            acc[0] = fmaf(f0.x, w, acc[0]);
            acc[1] = fmaf(f0.y, w, acc[1]);
            acc[2] = fmaf(f0.z, w, acc[2]);
            acc[3] = fmaf(f0.w, w, acc[3]);
            acc[4] = fmaf(f1.x, w, acc[4]);
            acc[5] = fmaf(f1.y, w, acc[5]);
            acc[6] = fmaf(f1.z, w, acc[6]);
            acc[7] = fmaf(f1.w, w, acc[7]);
        }
        __syncthreads();
    }

    float* dst = h1p + ((size_t)chunk * B_ + b0) * H1;
    #pragma unroll
    for (int m = 0; m < TM; m++)
        dst[m * H1 + j] = acc[m];
}

// ---------------------------------------------------------------------------
// Kernel 3: sum partials + bias + relu, stages 2/3, softmax.
// grid = B/TM, 256 threads.
// ---------------------------------------------------------------------------
__global__ __launch_bounds__(256) void finish_kernel(
    const float* __restrict__ h1p,
    const float* __restrict__ b1,
    const float* __restrict__ W2, const float* __restrict__ b2,
    const float* __restrict__ W3, const float* __restrict__ b3,
    float*       __restrict__ out)
{
    __shared__ float sh1[TM * H1];   // 8 KB
    __shared__ float sh2[TM * H2];   // 2 KB

    const int j  = threadIdx.x;
    const int b0 = blockIdx.x * TM;

    const float bias = b1[j];
    #pragma unroll
    for (int m = 0; m < TM; m++) {
        const size_t off = (size_t)(b0 + m) * H1 + j;
        float v = h1p[off] + h1p[(size_t)B_ * H1 + off] + h1p[2 * (size_t)B_ * H1 + off] + bias;
        sh1[m * H1 + j] = fmaxf(v, 0.f);
    }
    __syncthreads();

    // stage 2: h2 = relu(h1 @ W2 + b2); thread (m-group, j2) pattern
    {
        const int j2 = j & 63;
        for (int m = j >> 6; m < TM; m += 4) {
            float a = b2[j2];
            #pragma unroll 8
            for (int k = 0; k < H1; k++)
                a = fmaf(sh1[m * H1 + k], W2[(size_t)k * H2 + j2], a);
            sh2[m * H2 + j2] = fmaxf(a, 0.f);
        }
    }
    __syncthreads();

    // stage 3 + softmax: one thread per batch
    if (j < TM) {
        const int m = j;
        float l0 = b3[0], l1 = b3[1], l2 = b3[2], l3 = b3[3];
        #pragma unroll 8
        for (int k = 0; k < H2; k++) {
            const float h = sh2[m * H2 + k];
            l0 = fmaf(h, W3[k * NC + 0], l0);
            l1 = fmaf(h, W3[k * NC + 1], l1);
            l2 = fmaf(h, W3[k * NC + 2], l2);
            l3 = fmaf(h, W3[k * NC + 3], l3);
        }
        const float mx = fmaxf(fmaxf(l0, l1), fmaxf(l2, l3));
        const float e0 = __expf(l0 - mx), e1v = __expf(l1 - mx);
        const float e2v = __expf(l2 - mx), e3v = __expf(l3 - mx);
        const float inv = 1.0f / (e0 + e1v + e2v + e3v);
        float* o = out + (size_t)(b0 + m) * NC;
        o[0] = e0 * inv; o[1] = e1v * inv; o[2] = e2v * inv; o[3] = e3v * inv;
    }
}

// ---------------------------------------------------------------------------
extern "C" void kernel_launch(void* const* d_in, const int* in_sizes, int n_in,
                              void* d_out, int out_size)
{
    const float* x       = (const float*)d_in[0];
    const int*   e1_span = (const int*)  d_in[1];
    const int*   e2_span = (const int*)  d_in[2];
    const float* W1      = (const float*)d_in[3];
    const float* b1      = (const float*)d_in[4];
    const float* W2      = (const float*)d_in[5];
    const float* b2      = (const float*)d_in[6];
    const float* W3      = (const float*)d_in[7];
    const float* b3      = (const float*)d_in[8];
    float* out = (float*)d_out;

    float *feat, *h1p;
    cudaGetSymbolAddress((void**)&feat, g_feat);
    cudaGetSymbolAddress((void**)&h1p,  g_h1p);

    span_kernel <<<B_, 192>>>(x, e1_span, e2_span, feat);
    stage1_kernel<<<dim3(B_ / TM, KSPLIT), 256>>>(feat, W1, h1p);
    finish_kernel<<<B_ / TM, 256>>>(h1p, b1, W2, b2, W3, b3, out);
}

// round 4
// speedup vs baseline: 2.1478x; 1.2494x over previous
#include <cuda_runtime.h>
#include <math.h>

#define B_ 1024
#define S_ 512
#define D_ 768
#define FEAT 2304      // 3*D
#define H1 256
#define H2 64
#define NC 4

#define CCH 4          // row-chunks per batch in span phase
#define CROWS 128      // rows per chunk (CCH*CROWS = S_)

#define TM1 16         // batches per stage1 block
#define KSPLIT 6
#define KCHUNK 384     // FEAT / KSPLIT
#define KT 32          // W1 k-tile staged in smem

#define TMF 4          // batches per finish block

// Scratch (static device globals; no allocation allowed)
__device__ float g_part[2 * CCH * B_ * D_];     // [e][c][b][f] raw span sums
__device__ float g_feat[B_ * FEAT];             // [b][e1|e2|cls]
__device__ float g_h1p[KSPLIT * B_ * H1];       // [chunk][b][j] stage1 partials

// ---------------------------------------------------------------------------
// packed fp32x2 helpers (FFMA2 path — PTX-only on sm_103a)
// ---------------------------------------------------------------------------
__device__ __forceinline__ unsigned long long pack2(float lo, float hi) {
    unsigned long long u;
    asm("mov.b64 %0, {%1, %2};" : "=l"(u) : "f"(lo), "f"(hi));
    return u;
}
__device__ __forceinline__ void unpack2(unsigned long long u, float& lo, float& hi) {
    asm("mov.b64 {%0, %1}, %2;" : "=f"(lo), "=f"(hi) : "l"(u));
}
__device__ __forceinline__ void ffma2(unsigned long long& d, unsigned long long a,
                                      unsigned long long b, unsigned long long c) {
    asm("fma.rn.f32x2 %0, %1, %2, %3;" : "=l"(d) : "l"(a), "l"(b), "l"(c));
}

// ---------------------------------------------------------------------------
// Kernel 1: span partial sums over a fixed 128-row window.
// grid = (B, CCH), 192 threads; thread t owns float4 (cols 4t..4t+3).
// Always writes its partial (zeros if window misses the spans) -> deterministic.
// ---------------------------------------------------------------------------
__global__ __launch_bounds__(192) void span_chunk_kernel(
    const float* __restrict__ x,
    const int*   __restrict__ e1_span,
    const int*   __restrict__ e2_span,
    float*       __restrict__ part)
{
    const int b = blockIdx.x;
    const int c = blockIdx.y;
    const int t = threadIdx.x;

    int lo1 = e1_span[2 * b], hi1 = e1_span[2 * b + 1];
    if (hi1 < lo1 + 1) hi1 = lo1 + 1;
    int lo2 = e2_span[2 * b], hi2 = e2_span[2 * b + 1];
    if (hi2 < lo2 + 1) hi2 = lo2 + 1;

    const int w0 = c * CROWS;
    const int w1 = w0 + CROWS;

    const int u_lo = min(lo1, lo2);
    const int u_hi = max(hi1, hi2);
    int g_lo = min(hi1, hi2);
    int g_hi = max(lo1, lo2);
    if (g_hi < g_lo) { g_lo = u_hi; g_hi = u_hi; }   // overlap: no gap

    const float4* xb = (const float4*)(x + (size_t)b * S_ * D_);

    float4 a1 = make_float4(0.f, 0.f, 0.f, 0.f);
    float4 a2 = make_float4(0.f, 0.f, 0.f, 0.f);

    #pragma unroll 1
    for (int seg = 0; seg < 2; seg++) {
        const int s0 = max((seg == 0) ? u_lo : g_hi, w0);
        const int s1 = min((seg == 0) ? g_lo : u_hi, w1);
        int s = s0;
        for (; s + 4 <= s1; s += 4) {
            float4 r0 = xb[(size_t)(s + 0) * 192 + t];
            float4 r1 = xb[(size_t)(s + 1) * 192 + t];
            float4 r2 = xb[(size_t)(s + 2) * 192 + t];
            float4 r3 = xb[(size_t)(s + 3) * 192 + t];
            #pragma unroll
            for (int u = 0; u < 4; u++) {
                const int ss = s + u;
                const float4 r = (u == 0) ? r0 : (u == 1) ? r1 : (u == 2) ? r2 : r3;
                const float p1 = (ss >= lo1 && ss < hi1) ? 1.0f : 0.0f;
                const float p2 = (ss >= lo2 && ss < hi2) ? 1.0f : 0.0f;
                a1.x = fmaf(r.x, p1, a1.x); a1.y = fmaf(r.y, p1, a1.y);
                a1.z = fmaf(r.z, p1, a1.z); a1.w = fmaf(r.w, p1, a1.w);
                a2.x = fmaf(r.x, p2, a2.x); a2.y = fmaf(r.y, p2, a2.y);
                a2.z = fmaf(r.z, p2, a2.z); a2.w = fmaf(r.w, p2, a2.w);
            }
        }
        for (; s < s1; s++) {
            float4 r = xb[(size_t)s * 192 + t];
            const float p1 = (s >= lo1 && s < hi1) ? 1.0f : 0.0f;
            const float p2 = (s >= lo2 && s < hi2) ? 1.0f : 0.0f;
            a1.x = fmaf(r.x, p1, a1.x); a1.y = fmaf(r.y, p1, a1.y);
            a1.z = fmaf(r.z, p1, a1.z); a1.w = fmaf(r.w, p1, a1.w);
            a2.x = fmaf(r.x, p2, a2.x); a2.y = fmaf(r.y, p2, a2.y);
            a2.z = fmaf(r.z, p2, a2.z); a2.w = fmaf(r.w, p2, a2.w);
        }
    }

    float4* p1 = (float4*)(part + ((size_t)(0 * CCH + c) * B_ + b) * D_);
    float4* p2 = (float4*)(part + ((size_t)(1 * CCH + c) * B_ + b) * D_);
    p1[t] = a1;
    p2[t] = a2;
}

// ---------------------------------------------------------------------------
// Kernel 2: sum chunk partials, scale by 1/count, write feat; e==0 copies cls.
// grid = (B, 2), 192 threads.
// ---------------------------------------------------------------------------
__global__ __launch_bounds__(192) void span_reduce_kernel(
    const float* __restrict__ x,
    const int*   __restrict__ e1_span,
    const int*   __restrict__ e2_span,
    const float* __restrict__ part,
    float*       __restrict__ feat)
{
    const int b = blockIdx.x;
    const int e = blockIdx.y;
    const int t = threadIdx.x;

    const int* sp = (e == 0) ? e1_span : e2_span;
    int lo = sp[2 * b], hi = sp[2 * b + 1];
    if (hi < lo + 1) hi = lo + 1;
    const float inv = 1.0f / (float)(hi - lo);

    const float4* pb = (const float4*)(part + ((size_t)e * CCH * B_ + b) * D_);
    float4 s = make_float4(0.f, 0.f, 0.f, 0.f);
    #pragma unroll
    for (int c = 0; c < CCH; c++) {
        float4 v = pb[(size_t)c * B_ * (D_ / 4) + t];
        s.x += v.x; s.y += v.y; s.z += v.z; s.w += v.w;
    }
    float4* fb = (float4*)(feat + (size_t)b * FEAT);
    fb[e * 192 + t] = make_float4(s.x * inv, s.y * inv, s.z * inv, s.w * inv);

    if (e == 0) {
        const float4* xb = (const float4*)(x + (size_t)b * S_ * D_);
        fb[384 + t] = xb[t];   // cls = row 0
    }
}

// ---------------------------------------------------------------------------
// Kernel 3: stage-1 GEMM partials with packed f32x2 FMA.
// grid = (B/TM1, KSPLIT), 256 threads; thread j = h1 column.
// feat tile stored in smem as packed f32 pairs (batches 2p, 2p+1).
// ---------------------------------------------------------------------------
__global__ __launch_bounds__(256) void stage1_kernel(
    const float* __restrict__ feat,
    const float* __restrict__ W1,
    float*       __restrict__ h1p)
{
    __shared__ unsigned long long sfP[KCHUNK * (TM1 / 2)];  // 24 KB, [k][pair]
    __shared__ float sW[KT * H1];                           // 32 KB

    const int j     = threadIdx.x;
    const int b0    = blockIdx.x * TM1;
    const int chunk = blockIdx.y;

    // stage feat tile, pre-packed into f32 pairs
    const float* fbase = feat + (size_t)b0 * FEAT + chunk * KCHUNK;
    for (int idx = j; idx < KCHUNK * (TM1 / 2); idx += 256) {
        const int p = idx & (TM1 / 2 - 1);
        const int k = idx >> 3;                 // TM1/2 == 8
        const float v0 = fbase[(size_t)(2 * p + 0) * FEAT + k];
        const float v1 = fbase[(size_t)(2 * p + 1) * FEAT + k];
        sfP[idx] = pack2(v0, v1);
    }

    unsigned long long acc[TM1 / 2];
    #pragma unroll
    for (int p = 0; p < TM1 / 2; p++) acc[p] = 0ULL;

    const float* W1c = W1 + (size_t)chunk * KCHUNK * H1;

    __syncthreads();

    for (int kt = 0; kt < KCHUNK; kt += KT) {
        // stage W tile (KT x 256) via float4, coalesced: 8 float4 per thread
        {
            const float4* src = (const float4*)(W1c + (size_t)kt * H1);
            float4*       dst = (float4*)sW;
            #pragma unroll
            for (int i = 0; i < (KT * H1 / 4) / 256; i++)
                dst[j + i * 256] = src[j + i * 256];
        }
        __syncthreads();

        #pragma unroll
        for (int kk = 0; kk < KT; kk++) {
            const float w = sW[kk * H1 + j];
            const unsigned long long wp = pack2(w, w);
            const ulonglong2* fr = (const ulonglong2*)&sfP[(kt + kk) * (TM1 / 2)];
            ulonglong2 f01 = fr[0];
            ulonglong2 f23 = fr[1];
            ulonglong2 f45 = fr[2];
            ulonglong2 f67 = fr[3];
            ffma2(acc[0], f01.x, wp, acc[0]);
            ffma2(acc[1], f01.y, wp, acc[1]);
            ffma2(acc[2], f23.x, wp, acc[2]);
            ffma2(acc[3], f23.y, wp, acc[3]);
            ffma2(acc[4], f45.x, wp, acc[4]);
            ffma2(acc[5], f45.y, wp, acc[5]);
            ffma2(acc[6], f67.x, wp, acc[6]);
            ffma2(acc[7], f67.y, wp, acc[7]);
        }
        __syncthreads();
    }

    float* dst = h1p + ((size_t)chunk * B_ + b0) * H1;
    #pragma unroll
    for (int p = 0; p < TM1 / 2; p++) {
        float lo, hi;
        unpack2(acc[p], lo, hi);
        dst[(2 * p + 0) * H1 + j] = lo;
        dst[(2 * p + 1) * H1 + j] = hi;
    }
}

// ---------------------------------------------------------------------------
// Kernel 4: sum split-K partials + bias + relu, stage 2, stage 3 + softmax.
// grid = B/TMF, 256 threads.
// ---------------------------------------------------------------------------
__global__ __launch_bounds__(256) void finish_kernel(
    const float* __restrict__ h1p,
    const float* __restrict__ b1,
    const float* __restrict__ W2, const float* __restrict__ b2,
    const float* __restrict__ W3, const float* __restrict__ b3,
    float*       __restrict__ out)
{
    __shared__ float sh1[TMF * H1];
    __shared__ float sh2[TMF * H2];

    const int j  = threadIdx.x;
    const int b0 = blockIdx.x * TMF;

    const float bias = b1[j];
    #pragma unroll
    for (int m = 0; m < TMF; m++) {
        const size_t off = (size_t)(b0 + m) * H1 + j;
        float v = bias;
        #pragma unroll
        for (int c = 0; c < KSPLIT; c++)
            v += h1p[(size_t)c * B_ * H1 + off];
        sh1[m * H1 + j] = fmaxf(v, 0.f);
    }
    __syncthreads();

    // stage 2: one (batch m, column j2) per thread: 256 = TMF(4) * H2(64)
    {
        const int m  = j >> 6;
        const int j2 = j & 63;
        float a = b2[j2];
        #pragma unroll 8
        for (int k = 0; k < H1; k++)
            a = fmaf(sh1[m * H1 + k], W2[(size_t)k * H2 + j2], a);
        sh2[m * H2 + j2] = fmaxf(a, 0.f);
    }
    __syncthreads();

    // stage 3 + softmax: one thread per batch
    if (j < TMF) {
        const int m = j;
        float l0 = b3[0], l1 = b3[1], l2 = b3[2], l3 = b3[3];
        #pragma unroll 8
        for (int k = 0; k < H2; k++) {
            const float h = sh2[m * H2 + k];
            l0 = fmaf(h, W3[k * NC + 0], l0);
            l1 = fmaf(h, W3[k * NC + 1], l1);
            l2 = fmaf(h, W3[k * NC + 2], l2);
            l3 = fmaf(h, W3[k * NC + 3], l3);
        }
        const float mx = fmaxf(fmaxf(l0, l1), fmaxf(l2, l3));
        const float e0 = __expf(l0 - mx), e1v = __expf(l1 - mx);
        const float e2v = __expf(l2 - mx), e3v = __expf(l3 - mx);
        const float inv = 1.0f / (e0 + e1v + e2v + e3v);
        float* o = out + (size_t)(b0 + m) * NC;
        o[0] = e0 * inv; o[1] = e1v * inv; o[2] = e2v * inv; o[3] = e3v * inv;
    }
}

// ---------------------------------------------------------------------------
extern "C" void kernel_launch(void* const* d_in, const int* in_sizes, int n_in,
                              void* d_out, int out_size)
{
    const float* x       = (const float*)d_in[0];
    const int*   e1_span = (const int*)  d_in[1];
    const int*   e2_span = (const int*)  d_in[2];
    const float* W1      = (const float*)d_in[3];
    const float* b1      = (const float*)d_in[4];
    const float* W2      = (const float*)d_in[5];
    const float* b2      = (const float*)d_in[6];
    const float* W3      = (const float*)d_in[7];
    const float* b3      = (const float*)d_in[8];
    float* out = (float*)d_out;

    float *part, *feat, *h1p;
    cudaGetSymbolAddress((void**)&part, g_part);
    cudaGetSymbolAddress((void**)&feat, g_feat);
    cudaGetSymbolAddress((void**)&h1p,  g_h1p);

    span_chunk_kernel <<<dim3(B_, CCH), 192>>>(x, e1_span, e2_span, part);
    span_reduce_kernel<<<dim3(B_, 2),   192>>>(x, e1_span, e2_span, part, feat);
    stage1_kernel     <<<dim3(B_ / TM1, KSPLIT), 256>>>(feat, W1, h1p);
    finish_kernel     <<<B_ / TMF, 256>>>(h1p, b1, W2, b2, W3, b3, out);
}